// round 12
// baseline (speedup 1.0000x reference)
#include <cuda_runtime.h>

// ---------------------------------------------------------------------------
// YOLOv3 detection post-process, round 12: 4 kernels.
//  k_conf:        float4 conf pass (MLP 2); logit>2 pre-filter append;
//                 last-done block: hist+suffix-scan -> cutbits, filter, Mv.
//  k_decode_rank: keys staged in smem; warp/finalist sort-free rank + decode.
//  k_iou:         128 blocks; smem-staged boxes; 512x512 iou bit-matrix.
//  k_nms_out:     1 block; PIPELINED chunked greedy (warp w owns chunk w,
//                 spin-flags instead of barriers) + bulk early-exit.
// ---------------------------------------------------------------------------

#define NTOT    340704
#define N13     16224      // 32*3*13*13
#define OFF26   16224
#define OFF52   81120      // N13 + N26
#define CAP     4096
#define NBINS   4096
#define TOPK    512
#define PRECAP  32768
#define PRELOG  2.0f          // conf > sigmoid(2) = 0.8808; cutoff ~0.95

// slot layout for k_conf: float4 slots for 52/26 scales, scalar for 13
#define S52     64896         // 96 planes * 676 float4
#define S26     16224         // 96 planes * 169 float4
#define S13     16224         // 96 planes * 169 scalar (HW=169 odd)
#define SLOTS   (S52 + S26 + S13)   // 97344

__device__ unsigned            g_done;            // self-resetting
__device__ unsigned            g_precount;        // reset by conf tail
__device__ unsigned long long  g_pre[PRECAP];
__device__ unsigned            g_count;           // reset by k_nms_out
__device__ unsigned long long  g_keys[CAP];
__device__ int                 g_Mv;
__device__ float               g_cand[TOPK * 7];  // rank-indexed
__device__ unsigned            g_mask[TOPK * 16];

__constant__ float c_anchors[3][3][2] = {
    {{116.f, 90.f}, {156.f, 198.f}, {373.f, 326.f}},   // 13x13, stride 32
    {{ 30.f, 61.f}, { 62.f,  45.f}, { 59.f, 119.f}},   // 26x26, stride 16
    {{ 10.f, 13.f}, { 16.f,  30.f}, { 33.f,  23.f}}};  // 52x52, stride 8
__constant__ float c_stride[3] = {32.f, 16.f, 8.f};

__device__ __forceinline__ float sigm(float x) { return 1.0f / (1.0f + expf(-x)); }

// ---------------------------------------------------------------------------
__device__ __forceinline__ void conf_slot(int s,
                                          const float* __restrict__ in13,
                                          const float* __restrict__ in26,
                                          const float* __restrict__ in52,
                                          unsigned long long* keys,
                                          unsigned* slots, int& nk,
                                          unsigned* blk_cnt) {
    float v[4];
    int nv, b, a, HW, p0, goff;
    if (s < S52) {
        int plane = s / 676; int q = s - plane * 676;
        HW = 2704; p0 = q * 4; nv = 4; goff = OFF52;
        b = plane / 3; a = plane - b * 3;
        float4 f4 = *reinterpret_cast<const float4*>(
            in52 + (b * 255 + a * 85 + 4) * 2704 + p0);
        v[0] = f4.x; v[1] = f4.y; v[2] = f4.z; v[3] = f4.w;
    } else if (s < S52 + S26) {
        int s2 = s - S52;
        int plane = s2 / 169; int q = s2 - plane * 169;
        HW = 676; p0 = q * 4; nv = 4; goff = OFF26;
        b = plane / 3; a = plane - b * 3;
        float4 f4 = *reinterpret_cast<const float4*>(
            in26 + (b * 255 + a * 85 + 4) * 676 + p0);
        v[0] = f4.x; v[1] = f4.y; v[2] = f4.z; v[3] = f4.w;
    } else {
        int s2 = s - S52 - S26;
        int plane = s2 / 169; int q = s2 - plane * 169;
        HW = 169; p0 = q; nv = 1; goff = 0;
        b = plane / 3; a = plane - b * 3;
        v[0] = in13[(b * 255 + a * 85 + 4) * 169 + p0];   // scalar (odd HW)
    }
#pragma unroll
    for (int k = 0; k < 4; k++) {
        if (k >= nv) break;
        if (v[k] > PRELOG) {
            float conf = sigm(v[k]);
            unsigned g = (unsigned)(goff + (b * HW + p0 + k) * 3 + a);
            keys[nk]  = ((unsigned long long)__float_as_uint(conf) << 32)
                      | (0xFFFFFFFFu - g);
            slots[nk] = atomicAdd(blk_cnt, 1u);
            nk++;
        }
    }
}

__global__ void __launch_bounds__(256) k_conf(const float* __restrict__ in13,
                                              const float* __restrict__ in26,
                                              const float* __restrict__ in52) {
    __shared__ unsigned blk_cnt, blk_base;
    __shared__ bool is_last;
    __shared__ unsigned hist[NBINS];       // tail only; 16 KB
    __shared__ unsigned S[256];
    __shared__ unsigned s_cutbits, s_cnt;

    int tid = threadIdx.x;
    if (tid == 0) blk_cnt = 0u;
    __syncthreads();

    unsigned long long keys[8];
    unsigned slots[8];
    int nk = 0;
    int s0 = blockIdx.x * 512 + tid;
    if (s0 < SLOTS) conf_slot(s0, in13, in26, in52, keys, slots, nk, &blk_cnt);
    int s1 = s0 + 256;
    if (s1 < SLOTS) conf_slot(s1, in13, in26, in52, keys, slots, nk, &blk_cnt);

    __syncthreads();
    if (tid == 0 && blk_cnt > 0u)
        blk_base = atomicAdd(&g_precount, blk_cnt);
    __syncthreads();
    for (int k = 0; k < nk; k++) {
        unsigned pos = blk_base + slots[k];
        if (pos < PRECAP) g_pre[pos] = keys[k];
    }

    // ---- last-done block runs the cutoff + filter tail ---------------------
    __threadfence();
    if (tid == 0) {
        unsigned d = atomicAdd(&g_done, 1u);
        is_last = (d == gridDim.x - 1);
    }
    __syncthreads();
    if (!is_last) return;

    if (tid == 0) g_done = 0u;
    __threadfence();
    int P = (int)atomicAdd(&g_precount, 0u);
    if (P > PRECAP) P = PRECAP;

#pragma unroll
    for (int k = 0; k < NBINS / 256; k++) hist[tid + k * 256] = 0u;
    __syncthreads();
    for (int i = tid; i < P; i += 256) {
        unsigned bits = (unsigned)(g_pre[i] >> 32);
        unsigned bin  = (bits - 0x3F000000u) >> 11;
        if (bin > NBINS - 1) bin = NBINS - 1;
        atomicAdd(&hist[bin], 1u);
    }
    __syncthreads();

    unsigned loc[16];
    {
        unsigned ss = 0;
#pragma unroll
        for (int k = 0; k < 16; k++) { loc[k] = hist[tid * 16 + k]; ss += loc[k]; }
        S[tid] = ss;
    }
    for (int d = 1; d < 256; d <<= 1) {
        __syncthreads();
        unsigned add = (tid + d < 256) ? S[tid + d] : 0u;
        __syncthreads();
        S[tid] += add;
    }
    __syncthreads();
    if (tid == 0 && S[0] < TOPK) { s_cutbits = 0u; s_cnt = S[0]; }
    {
        unsigned Sn = (tid + 1 < 256) ? S[tid + 1] : 0u;
        if (S[tid] >= TOPK && Sn < TOPK) {           // exactly one tid
            unsigned cum = Sn;
            int cb = tid * 16;
            for (int k = 15; k >= 0; --k) {
                cum += loc[k];
                if (cum >= TOPK) { cb = tid * 16 + k; break; }
            }
            s_cutbits = 0x3F000000u + ((unsigned)cb << 11);
            s_cnt = cum;
        }
    }
    __syncthreads();
    unsigned cutbits = s_cutbits;
    if (tid == 0) {
        int c = (int)s_cnt;
        g_Mv = (c < TOPK) ? c : TOPK;
        g_precount = 0u;                             // ready for next replay
    }
    for (int i = tid; i < P; i += 256) {
        unsigned long long key = g_pre[i];
        if ((unsigned)(key >> 32) >= cutbits) {
            unsigned pos = atomicAdd(&g_count, 1u);
            if (pos < CAP) g_keys[pos] = key;
        }
    }
}

// ---------------------------------------------------------------------------
template<int HW, int W, int SC>
__device__ __forceinline__ void decode_one(const float* __restrict__ in,
                                           unsigned g, float conf, int lane,
                                           float* __restrict__ o) {
    int a  = g % 3;
    int p  = g / 3;
    int b  = p / HW;
    int pp = p - b * HW;
    int x  = pp % W;
    int y  = pp / W;
    const float* base = in + (b * 255 + a * 85) * HW + pp;
    float chv = (lane < 4) ? base[lane * HW] : 0.f;
    float bv = -3.4e38f; int bi = 127;
#pragma unroll
    for (int k = 0; k < 3; k++) {
        int c = lane + 32 * k;
        if (c < 80) {
            float v = base[(5 + c) * HW];
            if (v > bv) { bv = v; bi = c; }
        }
    }
#pragma unroll
    for (int off = 16; off; off >>= 1) {
        float ov = __shfl_xor_sync(0xFFFFFFFFu, bv, off);
        int   oi = __shfl_xor_sync(0xFFFFFFFFu, bi, off);
        if (ov > bv || (ov == bv && oi < bi)) { bv = ov; bi = oi; }
    }
    float t0 = __shfl_sync(0xFFFFFFFFu, chv, 0);
    float t1 = __shfl_sync(0xFFFFFFFFu, chv, 1);
    float t2 = __shfl_sync(0xFFFFFFFFu, chv, 2);
    float t3 = __shfl_sync(0xFFFFFFFFu, chv, 3);
    if (lane == 0) {
        float st = c_stride[SC];
        float cx = ((float)x + sigm(t0)) * st;
        float cy = ((float)y + sigm(t1)) * st;
        float w  = c_anchors[SC][a][0] * expf(t2);
        float h  = c_anchors[SC][a][1] * expf(t3);
        float w0 = w * 0.5f, h0 = h * 0.5f;
        o[0] = conf;
        o[1] = cx - w0;
        o[2] = cy - h0;
        o[3] = cx + w0;
        o[4] = cy + h0;
        o[5] = (float)bi;
        o[6] = (float)b;
    }
}

__global__ void __launch_bounds__(256) k_decode_rank(const float* __restrict__ in13,
                                                     const float* __restrict__ in26,
                                                     const float* __restrict__ in52) {
    __shared__ unsigned long long sk[CAP];     // 32 KB
    int tid = threadIdx.x;
    int M = (int)g_count; if (M > CAP) M = CAP;
    for (int i = tid; i < M; i += 256) sk[i] = g_keys[i];
    __syncthreads();

    int nwarps = gridDim.x * 8;
    int w0   = blockIdx.x * 8 + (tid >> 5);
    int lane = tid & 31;
    for (int i = w0; i < M; i += nwarps) {
        unsigned long long ki = sk[i];
        int rank = 0;
        for (int j0 = 0; j0 < M; j0 += 32) {
            int j = j0 + lane;
            unsigned long long kj = (j < M) ? sk[j] : 0ull;
            rank += __popc(__ballot_sync(0xFFFFFFFFu, (j < M) && (kj > ki)));
        }
        rank = __shfl_sync(0xFFFFFFFFu, rank, 0);
        if (rank >= TOPK) continue;
        float conf = __uint_as_float((unsigned)(ki >> 32));
        unsigned g = 0xFFFFFFFFu - (unsigned)(ki & 0xFFFFFFFFu);
        float* o = &g_cand[rank * 7];
        if (g < N13)        decode_one<169, 13, 0>(in13, g, conf, lane, o);
        else if (g < OFF52) decode_one<676, 26, 1>(in26, g - OFF26, conf, lane, o);
        else                decode_one<2704, 52, 2>(in52, g - OFF52, conf, lane, o);
    }
}

// ---------------------------------------------------------------------------
// 128 blocks x 512: smem-staged boxes, bit (i,j) = iou>thr && j>i (rank space).
__global__ void __launch_bounds__(512) k_iou() {
    __shared__ float sx1[TOPK], sy1[TOPK], sx2[TOPK], sy2[TOPK], sar[TOPK];
    int Mv = g_Mv;
    int j = threadIdx.x;
    {
        float x1 = 0.f, y1 = 0.f, x2 = 0.f, y2 = 0.f;
        if (j < Mv) {
            const float* c = &g_cand[j * 7];
            x1 = c[1]; y1 = c[2]; x2 = c[3]; y2 = c[4];
        }
        sx1[j] = x1; sy1[j] = y1; sx2[j] = x2; sy2[j] = y2;
        sar[j] = fmaxf(x2 - x1, 0.f) * fmaxf(y2 - y1, 0.f);
    }
    __syncthreads();

    bool jv = (j < Mv);
    float jx1 = sx1[j], jy1 = sy1[j], jx2 = sx2[j], jy2 = sy2[j], areaJ = sar[j];
    int wid = j >> 5, lane = j & 31;
#pragma unroll
    for (int q = 0; q < 4; q++) {
        int i = blockIdx.x * 4 + q;
        float xx1 = fmaxf(sx1[i], jx1), yy1 = fmaxf(sy1[i], jy1);
        float xx2 = fminf(sx2[i], jx2), yy2 = fminf(sy2[i], jy2);
        float inter = fmaxf(xx2 - xx1, 0.f) * fmaxf(yy2 - yy1, 0.f);
        float iou = inter / (sar[i] + areaJ - inter + 1e-9f);
        unsigned bal = __ballot_sync(0xFFFFFFFFu,
                                     jv && (i < Mv) && (j > i) && (iou > 0.3f));
        if (lane == 0) g_mask[i * 16 + wid] = bal;
    }
}

// ---------------------------------------------------------------------------
// Pipelined chunked greedy NMS: warp w owns ranks [32w, 32w+32); applies
// earlier chunks' kept rows as they publish (spin flags, no block barriers
// in the dependency chain). Exact greedy order preserved.
#define MW 17    // padded row stride
__global__ void __launch_bounds__(512) k_nms_out(float* __restrict__ out) {
    __shared__ unsigned sm[TOPK * MW];               // ~34.8 KB
    __shared__ volatile unsigned keptw[16];
    __shared__ volatile int      ready[16];
    int tid = threadIdx.x;
    int Mv = g_Mv;

    for (int r = tid; r < TOPK; r += 512) {
#pragma unroll
        for (int w = 0; w < 16; w++) sm[r * MW + w] = g_mask[r * 16 + w];
    }
    if (tid < 16) { keptw[tid] = 0u; ready[tid] = 0; }
    __syncthreads();

    int w = tid >> 5, lane = tid & 31;
    {
        // suppression word for chunk w, accumulated as earlier chunks publish
        unsigned sup = 0u;
        for (int k = 0; k < w; k++) {
            while (ready[k] == 0) { }                // spin on volatile smem
            unsigned kb = keptw[k];
            unsigned v = ((kb >> lane) & 1u) ? sm[(k * 32 + lane) * MW + w] : 0u;
            sup |= __reduce_or_sync(0xFFFFFFFFu, v);
        }
        // resolve own chunk
        unsigned rowdiag = sm[(w * 32 + lane) * MW + w]; // bits > lane only
        int lo = w * 32;
        unsigned valid;
        if (Mv >= lo + 32)      valid = 0xFFFFFFFFu;
        else if (Mv > lo)       valid = (1u << (Mv - lo)) - 1u;
        else                    valid = 0u;
        unsigned bits = ~sup & valid;                // warp-uniform
        unsigned kept = 0u;
        while (bits) {
            unsigned myrow = ((bits >> lane) & 1u) ? rowdiag : 0u;
            unsigned anysup = __reduce_or_sync(0xFFFFFFFFu, myrow);
            if ((bits & anysup) == 0u) { kept |= bits; break; }
            int b = __ffs(bits) - 1;                 // lowest bit always kept
            kept |= (1u << b);
            unsigned rw = __shfl_sync(0xFFFFFFFFu, rowdiag, b);
            bits = bits & ~(1u << b) & ~rw;
        }
        if (lane == 0) {
            keptw[w] = kept;
            __threadfence_block();
            ready[w] = 1;
        }
    }
    __syncthreads();

    if (tid == 0) g_count = 0u;                      // ready for next replay
    for (int idx = tid; idx < TOPK * 7; idx += 512) {
        int r = idx / 7;
        int c = idx - r * 7;
        float v = 0.f;
        if ((keptw[r >> 5] >> (r & 31)) & 1u)
            v = g_cand[r * 7 + c];
        out[idx] = v;
    }
}

// ---------------------------------------------------------------------------
extern "C" void kernel_launch(void* const* d_in, const int* in_sizes, int n_in,
                              void* d_out, int out_size) {
    const float* in13 = (const float*)d_in[0];
    const float* in26 = (const float*)d_in[1];
    const float* in52 = (const float*)d_in[2];
    float* out = (float*)d_out;

    k_conf       <<<(SLOTS + 511) / 512, 256>>>(in13, in26, in52);
    k_decode_rank<<<128, 256>>>(in13, in26, in52);
    k_iou        <<<128, 512>>>();
    k_nms_out    <<<1, 512>>>(out);
}

// round 13
// speedup vs baseline: 1.1824x; 1.1824x over previous
#include <cuda_runtime.h>

// ---------------------------------------------------------------------------
// YOLOv3 detection post-process, round 13: 4 kernels.
//  k_conf:        float4 conf pass; logit>2 pre-filter; last-done-block tail
//                 (hist + suffix scan -> cutbits, filter, Mv).
//  k_decode_rank: smem keys; warp/finalist rank + decode; also writes float4
//                 box array for k_iou.
//  k_iou:         128 blocks; float4 box staging; writes TRANSPOSED bitmask.
//  k_nms_out:     1 block; uint4-staged transposed mask; FIXED-POINT greedy
//                 (exact), ~2-4 rounds, no serial chain.
// ---------------------------------------------------------------------------

#define NTOT    340704
#define N13     16224      // 32*3*13*13
#define OFF26   16224
#define OFF52   81120      // N13 + N26
#define CAP     4096
#define NBINS   4096
#define TOPK    512
#define PRECAP  32768
#define PRELOG  2.0f          // conf > sigmoid(2) = 0.8808; cutoff ~0.95

// slot layout for k_conf: float4 slots for 52/26 scales, scalar for 13
#define S52     64896         // 96 planes * 676 float4
#define S26     16224         // 96 planes * 169 float4
#define S13     16224         // 96 planes * 169 scalar (HW=169 odd)
#define SLOTS   (S52 + S26 + S13)   // 97344

__device__ unsigned            g_done;            // self-resetting
__device__ unsigned            g_precount;        // reset by conf tail
__device__ unsigned long long  g_pre[PRECAP];
__device__ unsigned            g_count;           // reset by k_nms_out
__device__ unsigned long long  g_keys[CAP];
__device__ int                 g_Mv;
__device__ float               g_cand[TOPK * 7];  // rank-indexed
__device__ float4              g_box[TOPK];       // rank-indexed x1,y1,x2,y2
__device__ uint4               g_maskT4[TOPK * 16 / 4];  // transposed: word w of row i at [w*512+i]

__constant__ float c_anchors[3][3][2] = {
    {{116.f, 90.f}, {156.f, 198.f}, {373.f, 326.f}},   // 13x13, stride 32
    {{ 30.f, 61.f}, { 62.f,  45.f}, { 59.f, 119.f}},   // 26x26, stride 16
    {{ 10.f, 13.f}, { 16.f,  30.f}, { 33.f,  23.f}}};  // 52x52, stride 8
__constant__ float c_stride[3] = {32.f, 16.f, 8.f};

__device__ __forceinline__ float sigm(float x) { return 1.0f / (1.0f + expf(-x)); }

// ---------------------------------------------------------------------------
__device__ __forceinline__ void conf_slot(int s,
                                          const float* __restrict__ in13,
                                          const float* __restrict__ in26,
                                          const float* __restrict__ in52,
                                          unsigned long long* keys,
                                          unsigned* slots, int& nk,
                                          unsigned* blk_cnt) {
    float v[4];
    int nv, b, a, HW, p0, goff;
    if (s < S52) {
        int plane = s / 676; int q = s - plane * 676;
        HW = 2704; p0 = q * 4; nv = 4; goff = OFF52;
        b = plane / 3; a = plane - b * 3;
        float4 f4 = *reinterpret_cast<const float4*>(
            in52 + (b * 255 + a * 85 + 4) * 2704 + p0);
        v[0] = f4.x; v[1] = f4.y; v[2] = f4.z; v[3] = f4.w;
    } else if (s < S52 + S26) {
        int s2 = s - S52;
        int plane = s2 / 169; int q = s2 - plane * 169;
        HW = 676; p0 = q * 4; nv = 4; goff = OFF26;
        b = plane / 3; a = plane - b * 3;
        float4 f4 = *reinterpret_cast<const float4*>(
            in26 + (b * 255 + a * 85 + 4) * 676 + p0);
        v[0] = f4.x; v[1] = f4.y; v[2] = f4.z; v[3] = f4.w;
    } else {
        int s2 = s - S52 - S26;
        int plane = s2 / 169; int q = s2 - plane * 169;
        HW = 169; p0 = q; nv = 1; goff = 0;
        b = plane / 3; a = plane - b * 3;
        v[0] = in13[(b * 255 + a * 85 + 4) * 169 + p0];   // scalar (odd HW)
    }
#pragma unroll
    for (int k = 0; k < 4; k++) {
        if (k >= nv) break;
        if (v[k] > PRELOG) {
            float conf = sigm(v[k]);
            unsigned g = (unsigned)(goff + (b * HW + p0 + k) * 3 + a);
            keys[nk]  = ((unsigned long long)__float_as_uint(conf) << 32)
                      | (0xFFFFFFFFu - g);
            slots[nk] = atomicAdd(blk_cnt, 1u);
            nk++;
        }
    }
}

__global__ void __launch_bounds__(256) k_conf(const float* __restrict__ in13,
                                              const float* __restrict__ in26,
                                              const float* __restrict__ in52) {
    __shared__ unsigned blk_cnt, blk_base;
    __shared__ bool is_last;
    __shared__ unsigned hist[NBINS];       // tail only; 16 KB
    __shared__ unsigned S[256];
    __shared__ unsigned s_cutbits, s_cnt;

    int tid = threadIdx.x;
    if (tid == 0) blk_cnt = 0u;
    __syncthreads();

    unsigned long long keys[8];
    unsigned slots[8];
    int nk = 0;
    int s0 = blockIdx.x * 512 + tid;
    if (s0 < SLOTS) conf_slot(s0, in13, in26, in52, keys, slots, nk, &blk_cnt);
    int s1 = s0 + 256;
    if (s1 < SLOTS) conf_slot(s1, in13, in26, in52, keys, slots, nk, &blk_cnt);

    __syncthreads();
    if (tid == 0 && blk_cnt > 0u)
        blk_base = atomicAdd(&g_precount, blk_cnt);
    __syncthreads();
    for (int k = 0; k < nk; k++) {
        unsigned pos = blk_base + slots[k];
        if (pos < PRECAP) g_pre[pos] = keys[k];
    }

    // ---- last-done block runs the cutoff + filter tail ---------------------
    __threadfence();
    if (tid == 0) {
        unsigned d = atomicAdd(&g_done, 1u);
        is_last = (d == gridDim.x - 1);
    }
    __syncthreads();
    if (!is_last) return;

    if (tid == 0) g_done = 0u;
    __threadfence();
    int P = (int)atomicAdd(&g_precount, 0u);
    if (P > PRECAP) P = PRECAP;

#pragma unroll
    for (int k = 0; k < NBINS / 256; k++) hist[tid + k * 256] = 0u;
    __syncthreads();
    for (int i = tid; i < P; i += 256) {
        unsigned bits = (unsigned)(g_pre[i] >> 32);
        unsigned bin  = (bits - 0x3F000000u) >> 11;
        if (bin > NBINS - 1) bin = NBINS - 1;
        atomicAdd(&hist[bin], 1u);
    }
    __syncthreads();

    unsigned loc[16];
    {
        unsigned ss = 0;
#pragma unroll
        for (int k = 0; k < 16; k++) { loc[k] = hist[tid * 16 + k]; ss += loc[k]; }
        S[tid] = ss;
    }
    for (int d = 1; d < 256; d <<= 1) {
        __syncthreads();
        unsigned add = (tid + d < 256) ? S[tid + d] : 0u;
        __syncthreads();
        S[tid] += add;
    }
    __syncthreads();
    if (tid == 0 && S[0] < TOPK) { s_cutbits = 0u; s_cnt = S[0]; }
    {
        unsigned Sn = (tid + 1 < 256) ? S[tid + 1] : 0u;
        if (S[tid] >= TOPK && Sn < TOPK) {           // exactly one tid
            unsigned cum = Sn;
            int cb = tid * 16;
            for (int k = 15; k >= 0; --k) {
                cum += loc[k];
                if (cum >= TOPK) { cb = tid * 16 + k; break; }
            }
            s_cutbits = 0x3F000000u + ((unsigned)cb << 11);
            s_cnt = cum;
        }
    }
    __syncthreads();
    unsigned cutbits = s_cutbits;
    if (tid == 0) {
        int c = (int)s_cnt;
        g_Mv = (c < TOPK) ? c : TOPK;
        g_precount = 0u;                             // ready for next replay
    }
    for (int i = tid; i < P; i += 256) {
        unsigned long long key = g_pre[i];
        if ((unsigned)(key >> 32) >= cutbits) {
            unsigned pos = atomicAdd(&g_count, 1u);
            if (pos < CAP) g_keys[pos] = key;
        }
    }
}

// ---------------------------------------------------------------------------
template<int HW, int W, int SC>
__device__ __forceinline__ void decode_one(const float* __restrict__ in,
                                           unsigned g, float conf, int lane,
                                           int rank) {
    int a  = g % 3;
    int p  = g / 3;
    int b  = p / HW;
    int pp = p - b * HW;
    int x  = pp % W;
    int y  = pp / W;
    const float* base = in + (b * 255 + a * 85) * HW + pp;
    float chv = (lane < 4) ? base[lane * HW] : 0.f;
    float bv = -3.4e38f; int bi = 127;
#pragma unroll
    for (int k = 0; k < 3; k++) {
        int c = lane + 32 * k;
        if (c < 80) {
            float v = base[(5 + c) * HW];
            if (v > bv) { bv = v; bi = c; }
        }
    }
#pragma unroll
    for (int off = 16; off; off >>= 1) {
        float ov = __shfl_xor_sync(0xFFFFFFFFu, bv, off);
        int   oi = __shfl_xor_sync(0xFFFFFFFFu, bi, off);
        if (ov > bv || (ov == bv && oi < bi)) { bv = ov; bi = oi; }
    }
    float t0 = __shfl_sync(0xFFFFFFFFu, chv, 0);
    float t1 = __shfl_sync(0xFFFFFFFFu, chv, 1);
    float t2 = __shfl_sync(0xFFFFFFFFu, chv, 2);
    float t3 = __shfl_sync(0xFFFFFFFFu, chv, 3);
    if (lane == 0) {
        float st = c_stride[SC];
        float cx = ((float)x + sigm(t0)) * st;
        float cy = ((float)y + sigm(t1)) * st;
        float w  = c_anchors[SC][a][0] * expf(t2);
        float h  = c_anchors[SC][a][1] * expf(t3);
        float w0 = w * 0.5f, h0 = h * 0.5f;
        float x1 = cx - w0, y1 = cy - h0, x2 = cx + w0, y2 = cy + h0;
        float* o = &g_cand[rank * 7];
        o[0] = conf;
        o[1] = x1; o[2] = y1; o[3] = x2; o[4] = y2;
        o[5] = (float)bi;
        o[6] = (float)b;
        g_box[rank] = make_float4(x1, y1, x2, y2);
    }
}

__global__ void __launch_bounds__(256) k_decode_rank(const float* __restrict__ in13,
                                                     const float* __restrict__ in26,
                                                     const float* __restrict__ in52) {
    __shared__ unsigned long long sk[CAP];     // 32 KB
    int tid = threadIdx.x;
    int M = (int)g_count; if (M > CAP) M = CAP;
    for (int i = tid; i < M; i += 256) sk[i] = g_keys[i];
    __syncthreads();

    int nwarps = gridDim.x * 8;
    int w0   = blockIdx.x * 8 + (tid >> 5);
    int lane = tid & 31;
    for (int i = w0; i < M; i += nwarps) {
        unsigned long long ki = sk[i];
        int rank = 0;
        for (int j0 = 0; j0 < M; j0 += 32) {
            int j = j0 + lane;
            unsigned long long kj = (j < M) ? sk[j] : 0ull;
            rank += __popc(__ballot_sync(0xFFFFFFFFu, (j < M) && (kj > ki)));
        }
        rank = __shfl_sync(0xFFFFFFFFu, rank, 0);
        if (rank >= TOPK) continue;
        float conf = __uint_as_float((unsigned)(ki >> 32));
        unsigned g = 0xFFFFFFFFu - (unsigned)(ki & 0xFFFFFFFFu);
        if (g < N13)        decode_one<169, 13, 0>(in13, g, conf, lane, rank);
        else if (g < OFF52) decode_one<676, 26, 1>(in26, g - OFF26, conf, lane, rank);
        else                decode_one<2704, 52, 2>(in52, g - OFF52, conf, lane, rank);
    }
}

// ---------------------------------------------------------------------------
// 128 blocks x 512: float4 box staging; writes TRANSPOSED mask
// g_maskT[w*512 + i] = word w (j-bits [32w,32w+32)) of row i;
// bit set iff iou(i,j)>thr && j>i, in rank space.
__global__ void __launch_bounds__(512) k_iou() {
    __shared__ float sx1[TOPK], sy1[TOPK], sx2[TOPK], sy2[TOPK], sar[TOPK];
    int Mv = g_Mv;
    int j = threadIdx.x;
    {
        float4 bx = (j < Mv) ? g_box[j] : make_float4(0.f, 0.f, 0.f, 0.f);
        sx1[j] = bx.x; sy1[j] = bx.y; sx2[j] = bx.z; sy2[j] = bx.w;
        sar[j] = fmaxf(bx.z - bx.x, 0.f) * fmaxf(bx.w - bx.y, 0.f);
    }
    __syncthreads();

    bool jv = (j < Mv);
    float jx1 = sx1[j], jy1 = sy1[j], jx2 = sx2[j], jy2 = sy2[j], areaJ = sar[j];
    int wid = j >> 5, lane = j & 31;
    unsigned* maskT = reinterpret_cast<unsigned*>(g_maskT4);
#pragma unroll
    for (int q = 0; q < 4; q++) {
        int i = blockIdx.x * 4 + q;
        float xx1 = fmaxf(sx1[i], jx1), yy1 = fmaxf(sy1[i], jy1);
        float xx2 = fminf(sx2[i], jx2), yy2 = fminf(sy2[i], jy2);
        float inter = fmaxf(xx2 - xx1, 0.f) * fmaxf(yy2 - yy1, 0.f);
        float iou = inter / (sar[i] + areaJ - inter + 1e-9f);
        unsigned bal = __ballot_sync(0xFFFFFFFFu,
                                     jv && (i < Mv) && (j > i) && (iou > 0.3f));
        if (lane == 0) maskT[wid * TOPK + i] = bal;
    }
}

// ---------------------------------------------------------------------------
// Fixed-point greedy NMS (exact). kept[j] final iff no kept i<j suppresses j.
// Round: newly-kept = und & ~OR(rows in kept|und); newly-dead = und & OR(kept
// rows). The smallest undetermined rank is determined every round -> exact,
// converges in a few rounds on sparse graphs.
__global__ void __launch_bounds__(512) k_nms_out(float* __restrict__ out) {
    __shared__ unsigned smT[16 * TOPK];        // 32 KB, [w*512 + i]
    __shared__ unsigned kept[16], und[16];
    __shared__ int done;
    int tid = threadIdx.x;
    int Mv = g_Mv;

    {   // uint4 bulk load (2048 LDG.128 / STS.128 total)
        uint4* dst = reinterpret_cast<uint4*>(smT);
        for (int idx = tid; idx < 16 * TOPK / 4; idx += 512)
            dst[idx] = g_maskT4[idx];
    }
    if (tid < 16) {
        int lo = tid * 32;
        unsigned v;
        if (Mv >= lo + 32)      v = 0xFFFFFFFFu;
        else if (Mv > lo)       v = (1u << (Mv - lo)) - 1u;
        else                    v = 0u;
        und[tid] = v; kept[tid] = 0u;
    }
    __syncthreads();

    int w = tid >> 5, lane = tid & 31;
    for (int round = 0; round < TOPK; round++) {
        unsigned sk = 0u, pk = 0u;
#pragma unroll
        for (int k = 0; k < 16; k++) {
            unsigned kb = kept[k];
            unsigned ab = kb | und[k];
            unsigned row = smT[w * TOPK + k * 32 + lane];   // conflict-free
            if ((kb >> lane) & 1u) sk |= row;
            if ((ab >> lane) & 1u) pk |= row;
        }
        sk = __reduce_or_sync(0xFFFFFFFFu, sk);
        pk = __reduce_or_sync(0xFFFFFFFFu, pk);
        __syncthreads();
        if (lane == 0) {
            unsigned u = und[w];
            kept[w] |= u & ~pk;          // no possible suppressor -> kept
            und[w]   = u & pk & ~sk;     // definite suppressor -> dead
        }
        __syncthreads();
        if (tid == 0) {
            unsigned any = 0u;
#pragma unroll
            for (int k = 0; k < 16; k++) any |= und[k];
            done = (any == 0u);
        }
        __syncthreads();
        if (done) break;
    }

    if (tid == 0) g_count = 0u;                      // ready for next replay
    for (int idx = tid; idx < TOPK * 7; idx += 512) {
        int r = idx / 7;
        int c = idx - r * 7;
        float v = 0.f;
        if ((kept[r >> 5] >> (r & 31)) & 1u)
            v = g_cand[r * 7 + c];
        out[idx] = v;
    }
}

// ---------------------------------------------------------------------------
extern "C" void kernel_launch(void* const* d_in, const int* in_sizes, int n_in,
                              void* d_out, int out_size) {
    const float* in13 = (const float*)d_in[0];
    const float* in26 = (const float*)d_in[1];
    const float* in52 = (const float*)d_in[2];
    float* out = (float*)d_out;

    k_conf       <<<(SLOTS + 511) / 512, 256>>>(in13, in26, in52);
    k_decode_rank<<<128, 256>>>(in13, in26, in52);
    k_iou        <<<128, 512>>>();
    k_nms_out    <<<1, 512>>>(out);
}